// round 15
// baseline (speedup 1.0000x reference)
#include <cuda_runtime.h>
#include <cuda_fp16.h>
#include <math.h>

// ============================================================================
// ThermoQuantizer, single fused kernel. Round 15: bank-private replicated
// table -> conflict-free LDS gather.
//
// out = (1-p)*x + p * mean_c * f(x/mean_c)  ==  mean_c * G(xn)
// G tabulated at TN=384 nodes over [-10.5,10.5] (h=0.0547, same as R11) as
// half2(A_j, B_j); out = mean * (A_j + fr*B_j).
//
// KEY CHANGE: the table is replicated 32x, one copy per smem bank:
//   word index (j*32 + lane)  =>  bank == lane  for every j.
// Each lane only ever touches its own bank => every LDS.32 gather is ONE
// wavefront instead of ~3.2 conflict phases. L1 wavefront budget per KB
// drops 42 -> 24 (prev binding constraint at ~94% of service rate).
//
// Group abs-mean via fixed-point redux.sync.add.s32; floor/frac via the
// 2^23 trick; .cs streaming hints; 2 groups/warp-iter + next-pair prefetch.
// ============================================================================

#define TN      384
#define THALF   10.5f
#define TSCALE  ((float)TN / (2.0f * THALF))   // 18.2857 entries per unit xn
#define TOFF    ((float)TN * 0.5f)             // 192
#define FIXS    262144.0f                  // 2^18 fixed-point reduction scale
#define C23     8388608.0f                 // 2^23
#define BIGOFF  (TOFF - 0.5f + C23)        // fma addend for floor-extract
#define K2      (TOFF + C23)               // for fr reconstruction
#define IBASE   0x4B000000                 // bit pattern of 2^23

__device__ __forceinline__ float rcp_approx(float x) {
    float r;
    asm("rcp.approx.f32 %0, %1;" : "=f"(r) : "f"(x));
    return r;
}
__device__ __forceinline__ int warp_sum_i(int x) {
    int r;
    asm("redux.sync.add.s32 %0, %1, 0xffffffff;" : "=r"(r) : "r"(x));
    return r;
}
__device__ __forceinline__ float4 ldcs4(const float4* p) {
    float4 v;
    asm("ld.global.cs.v4.f32 {%0,%1,%2,%3}, [%4];"
        : "=f"(v.x), "=f"(v.y), "=f"(v.z), "=f"(v.w) : "l"(p));
    return v;
}
__device__ __forceinline__ void stcs4(float4* p, float4 v) {
    asm("st.global.cs.v4.f32 [%0], {%1,%2,%3,%4};"
        :: "l"(p), "f"(v.x), "f"(v.y), "f"(v.z), "f"(v.w) : "memory");
}

extern __shared__ __half2 tbl[];           // TN*32 entries, bank-private

__global__ __launch_bounds__(512, 2)
void tq_fused(const float4* __restrict__ x4, float4* __restrict__ out4,
              const float* __restrict__ cb, const float* __restrict__ pressure,
              const float* __restrict__ temp, int ngroups) {
    __shared__ float vals[TN + 1];

    int lane = threadIdx.x & 31;
    int w    = blockIdx.x * 16 + (threadIdx.x >> 5);
    int W    = gridDim.x * 16;
    int step = 2 * W;

    // First pair's loads before the table build (latency hidden by build).
    int g = w * 2;                          // ngroups even => g+1 valid
    bool have = g < ngroups;
    const float4* src = x4   + (g << 5) + lane;
    float4*       dst = out4 + (g << 5) + lane;
    const long sstep = (long)step << 5;

    float4 v0, v1;
    if (have) {
        v0 = ldcs4(src);
        v1 = ldcs4(src + 32);
    }

    float p   = *pressure;
    float omp = 1.0f - p;

    // ---- Phase 1a: tabulate G(xn) = omp*xn + p*f(xn) at TN+1 nodes ----
    {
        float T = *temp + 1e-6f;
        float invT = 1.0f / T;
        float c[16];
#pragma unroll
        for (int i = 0; i < 16; i++) c[i] = cb[i];

        for (int j = threadIdx.x; j < TN + 1; j += 512) {
            float xn = -THALF + (float)j * (2.0f * THALF / (float)TN);
            float m = -3.4e38f;
            float lg[16];
#pragma unroll
            for (int i = 0; i < 16; i++) {
                float d = xn - c[i];
                lg[i] = -(d * d) * invT;
                m = fmaxf(m, lg[i]);
            }
            float sw = 0.0f, sc = 0.0f;
#pragma unroll
            for (int i = 0; i < 16; i++) {
                float wgt = __expf(lg[i] - m);
                sw += wgt;
                sc += wgt * c[i];
            }
            vals[j] = omp * xn + p * (sc / sw);   // G at node j
        }
    }
    __syncthreads();
    // ---- Phase 1b: replicate into 32 bank-private copies ----
    // word (j*32 + l) -> bank l. Consecutive tid -> consecutive banks: the
    // replication writes are conflict-free too.
    for (int idx = threadIdx.x; idx < TN * 32; idx += 512) {
        int j = idx >> 5;
        tbl[idx] = __floats2half2_rn(vals[j], vals[j + 1] - vals[j]);
    }
    __syncthreads();

    if (!have) return;

    const __half2* mytbl = tbl + lane;     // lane-private bank base

    // ---- Phase 2: stream; 2 groups per warp-iter, next pair prefetched ----
    while (true) {
        int gn = g + step;
        bool more = gn < ngroups;
        float4 n0, n1;
        if (more) {
            n0 = ldcs4(src + sstep);
            n1 = ldcs4(src + sstep + 32);
        }

        // fixed-point single-instruction warp reductions
        float a0 = fabsf(v0.x) + fabsf(v0.y) + fabsf(v0.z) + fabsf(v0.w);
        float a1 = fabsf(v1.x) + fabsf(v1.y) + fabsf(v1.z) + fabsf(v1.w);
        int i0 = warp_sum_i(__float2int_rn(a0 * FIXS));
        int i1 = warp_sum_i(__float2int_rn(a1 * FIXS));
        float mean0 = fmaxf((float)i0 * (1.0f / (FIXS * 128.0f)), 1e-5f);
        float mean1 = fmaxf((float)i1 * (1.0f / (FIXS * 128.0f)), 1e-5f);
        float ks0 = rcp_approx(mean0) * TSCALE;
        float ks1 = rcp_approx(mean1) * TSCALE;

        float4 o0, o1;
#define LOOKUP(OUT, VIN, KS, MEAN)                                            \
        {                                                                     \
            float big = fmaf((VIN), (KS), BIGOFF);    /* 2^23 + floor(u) */   \
            int   jx  = __float_as_int(big) - IBASE;  /* floor(u) */          \
            float s   = K2 - big;                     /* TOFF - jf */         \
            float fr  = fmaf((VIN), (KS), s);         /* u - floor(u) */      \
            float2 ab = __half22float2(mytbl[jx << 5]);  /* bank-private */   \
            (OUT) = (MEAN) * fmaf(fr, ab.y, ab.x);                            \
        }
        LOOKUP(o0.x, v0.x, ks0, mean0)
        LOOKUP(o1.x, v1.x, ks1, mean1)
        LOOKUP(o0.y, v0.y, ks0, mean0)
        LOOKUP(o1.y, v1.y, ks1, mean1)
        LOOKUP(o0.z, v0.z, ks0, mean0)
        LOOKUP(o1.z, v1.z, ks1, mean1)
        LOOKUP(o0.w, v0.w, ks0, mean0)
        LOOKUP(o1.w, v1.w, ks1, mean1)
#undef LOOKUP

        stcs4(dst, o0);
        stcs4(dst + 32, o1);

        if (!more) break;
        v0 = n0; v1 = n1; g = gn;
        src += sstep; dst += sstep;
    }
}

extern "C" void kernel_launch(void* const* d_in, const int* in_sizes, int n_in,
                              void* d_out, int out_size) {
    const float* x        = (const float*)d_in[0];
    const float* cb       = (const float*)d_in[1];
    const float* pressure = (const float*)d_in[2];
    const float* temp     = (const float*)d_in[3];

    int n = in_sizes[0];
    int ngroups = n / 128;

    int dyn_smem = TN * 32 * (int)sizeof(__half2);   // 48 KB
    cudaFuncSetAttribute(tq_fused,
                         cudaFuncAttributeMaxDynamicSharedMemorySize, dyn_smem);

    int blocks = 148 * 2;   // persistent grid-stride, 2 blocks/SM
    tq_fused<<<blocks, 512, dyn_smem>>>((const float4*)x, (float4*)d_out,
                                        cb, pressure, temp, ngroups);
}

// round 16
// speedup vs baseline: 1.0230x; 1.0230x over previous
#include <cuda_runtime.h>
#include <cuda_fp16.h>
#include <math.h>

// ============================================================================
// ThermoQuantizer, single fused kernel. Round 16: bank-private table +
// register-slim two-pass build -> 3 blocks/SM (48 warps).
//
// out = (1-p)*x + p * mean_c * f(x/mean_c)  ==  mean_c * G(xn)
// G tabulated at TN=384 nodes over [-10.5,10.5] as half2(A_j, B_j);
// out = mean * (A_j + fr*B_j). Table replicated 32x, one copy per smem
// bank (word j*32+lane -> bank==lane): every gather is conflict-free.
// Two-pass softmax build (min-d^2 shift, then exp-sum) keeps regs ~40 so
// three 512-thread blocks fit per SM. floor/frac via the 2^23 trick;
// abs-mean via redux.sync.add.s32; .cs hints; next-pair prefetch.
// ============================================================================

#define TN      384
#define THALF   10.5f
#define TSCALE  ((float)TN / (2.0f * THALF))
#define TOFF    ((float)TN * 0.5f)
#define FIXS    262144.0f                  // 2^18 fixed-point reduction scale
#define C23     8388608.0f                 // 2^23
#define BIGOFF  (TOFF - 0.5f + C23)        // fma addend for floor-extract
#define K2      (TOFF + C23)               // for fr reconstruction
#define IBASE   0x4B000000                 // bit pattern of 2^23

__device__ __forceinline__ float rcp_approx(float x) {
    float r;
    asm("rcp.approx.f32 %0, %1;" : "=f"(r) : "f"(x));
    return r;
}
__device__ __forceinline__ int warp_sum_i(int x) {
    int r;
    asm("redux.sync.add.s32 %0, %1, 0xffffffff;" : "=r"(r) : "r"(x));
    return r;
}
__device__ __forceinline__ float4 ldcs4(const float4* p) {
    float4 v;
    asm("ld.global.cs.v4.f32 {%0,%1,%2,%3}, [%4];"
        : "=f"(v.x), "=f"(v.y), "=f"(v.z), "=f"(v.w) : "l"(p));
    return v;
}
__device__ __forceinline__ void stcs4(float4* p, float4 v) {
    asm("st.global.cs.v4.f32 [%0], {%1,%2,%3,%4};"
        :: "l"(p), "f"(v.x), "f"(v.y), "f"(v.z), "f"(v.w) : "memory");
}

extern __shared__ __half2 tbl[];           // TN*32 entries, bank-private

__global__ __launch_bounds__(512, 3)
void tq_fused(const float4* __restrict__ x4, float4* __restrict__ out4,
              const float* __restrict__ cb, const float* __restrict__ pressure,
              const float* __restrict__ temp, int ngroups) {
    __shared__ float vals[TN + 1];

    float p   = *pressure;
    float omp = 1.0f - p;

    // ---- Phase 1a: tabulate G(xn) = omp*xn + p*f(xn), two-pass softmax ----
    {
        float T = *temp + 1e-6f;
        float invT = 1.0f / T;

        for (int j = threadIdx.x; j < TN + 1; j += 512) {
            float xn = -THALF + (float)j * (2.0f * THALF / (float)TN);
            // pass 1: min squared distance (softmax shift), no register array
            float mind2 = 3.4e38f;
#pragma unroll
            for (int i = 0; i < 16; i++) {
                float d = xn - __ldg(cb + i);
                mind2 = fminf(mind2, d * d);
            }
            // pass 2: shifted exp-sum
            float sw = 0.0f, sc = 0.0f;
#pragma unroll
            for (int i = 0; i < 16; i++) {
                float ci = __ldg(cb + i);
                float d  = xn - ci;
                float wgt = __expf((mind2 - d * d) * invT);
                sw += wgt;
                sc += wgt * ci;
            }
            vals[j] = omp * xn + p * (sc / sw);   // G at node j
        }
    }
    __syncthreads();
    // ---- Phase 1b: replicate into 32 bank-private copies ----
    for (int idx = threadIdx.x; idx < TN * 32; idx += 512) {
        int j = idx >> 5;
        tbl[idx] = __floats2half2_rn(vals[j], vals[j + 1] - vals[j]);
    }
    __syncthreads();

    int lane = threadIdx.x & 31;
    int w    = blockIdx.x * 16 + (threadIdx.x >> 5);
    int W    = gridDim.x * 16;
    int step = 2 * W;

    int g = w * 2;                          // ngroups even => g+1 valid
    if (g >= ngroups) return;
    const float4* src = x4   + (g << 5) + lane;
    float4*       dst = out4 + (g << 5) + lane;
    const long sstep = (long)step << 5;

    const __half2* mytbl = tbl + lane;      // lane-private bank base

    float4 v0 = ldcs4(src);
    float4 v1 = ldcs4(src + 32);

    // ---- Phase 2: stream; 2 groups per warp-iter, next pair prefetched ----
    while (true) {
        int gn = g + step;
        bool more = gn < ngroups;
        float4 n0, n1;
        if (more) {
            n0 = ldcs4(src + sstep);
            n1 = ldcs4(src + sstep + 32);
        }

        // fixed-point single-instruction warp reductions
        float a0 = fabsf(v0.x) + fabsf(v0.y) + fabsf(v0.z) + fabsf(v0.w);
        float a1 = fabsf(v1.x) + fabsf(v1.y) + fabsf(v1.z) + fabsf(v1.w);
        int i0 = warp_sum_i(__float2int_rn(a0 * FIXS));
        int i1 = warp_sum_i(__float2int_rn(a1 * FIXS));
        float mean0 = fmaxf((float)i0 * (1.0f / (FIXS * 128.0f)), 1e-5f);
        float mean1 = fmaxf((float)i1 * (1.0f / (FIXS * 128.0f)), 1e-5f);
        float ks0 = rcp_approx(mean0) * TSCALE;
        float ks1 = rcp_approx(mean1) * TSCALE;

        float4 o0, o1;
#define LOOKUP(OUT, VIN, KS, MEAN)                                            \
        {                                                                     \
            float big = fmaf((VIN), (KS), BIGOFF);    /* 2^23 + floor(u) */   \
            int   jx  = __float_as_int(big) - IBASE;  /* floor(u) */          \
            float s   = K2 - big;                     /* TOFF - jf */         \
            float fr  = fmaf((VIN), (KS), s);         /* u - floor(u) */      \
            float2 ab = __half22float2(mytbl[jx << 5]);  /* bank-private */   \
            (OUT) = (MEAN) * fmaf(fr, ab.y, ab.x);                            \
        }
        LOOKUP(o0.x, v0.x, ks0, mean0)
        LOOKUP(o1.x, v1.x, ks1, mean1)
        LOOKUP(o0.y, v0.y, ks0, mean0)
        LOOKUP(o1.y, v1.y, ks1, mean1)
        LOOKUP(o0.z, v0.z, ks0, mean0)
        LOOKUP(o1.z, v1.z, ks1, mean1)
        LOOKUP(o0.w, v0.w, ks0, mean0)
        LOOKUP(o1.w, v1.w, ks1, mean1)
#undef LOOKUP

        stcs4(dst, o0);
        stcs4(dst + 32, o1);

        if (!more) break;
        v0 = n0; v1 = n1; g = gn;
        src += sstep; dst += sstep;
    }
}

extern "C" void kernel_launch(void* const* d_in, const int* in_sizes, int n_in,
                              void* d_out, int out_size) {
    const float* x        = (const float*)d_in[0];
    const float* cb       = (const float*)d_in[1];
    const float* pressure = (const float*)d_in[2];
    const float* temp     = (const float*)d_in[3];

    int n = in_sizes[0];
    int ngroups = n / 128;

    int dyn_smem = TN * 32 * (int)sizeof(__half2);   // 48 KB
    cudaFuncSetAttribute(tq_fused,
                         cudaFuncAttributeMaxDynamicSharedMemorySize, dyn_smem);

    int blocks = 148 * 3;   // persistent grid-stride, 3 blocks/SM
    tq_fused<<<blocks, 512, dyn_smem>>>((const float4*)x, (float4*)d_out,
                                        cb, pressure, temp, ngroups);
}